// round 7
// baseline (speedup 1.0000x reference)
#include <cuda_runtime.h>
#include <cstdint>

#define NPTS 8192
#define FDIM 512
#define SEGS 32
#define SEGREFS 256

typedef unsigned long long ull;

// ---- device scratch (no allocations allowed) ----
__device__ float g_emb[1024 * NPTS];
__device__ float g_h1[2][640 * NPTS];
__device__ float g_h2[2][256 * NPTS];
__device__ float g_h3[2][128 * NPTS];
__device__ int   g_idx[NPTS];
__device__ ulonglong2 g_refp[NPTS / 2][2];   // {x01,y01},{z01,r2_01}
__device__ ull   g_part[SEGS * NPTS];

// ---- f32x2 helpers ----
__device__ __forceinline__ ull pack2(float lo, float hi) {
    ull r; asm("mov.b64 %0, {%1, %2};" : "=l"(r) : "f"(lo), "f"(hi)); return r;
}
__device__ __forceinline__ void unpack2(ull v, float& lo, float& hi) {
    asm("mov.b64 {%0, %1}, %2;" : "=f"(lo), "=f"(hi) : "l"(v));
}
__device__ __forceinline__ ull fma2(ull a, ull b, ull c) {
    ull d; asm("fma.rn.f32x2 %0, %1, %2, %3;" : "=l"(d) : "l"(a), "l"(b), "l"(c)); return d;
}
__device__ __forceinline__ ull mul2(ull a, ull b) {
    ull d; asm("mul.rn.f32x2 %0, %1, %2;" : "=l"(d) : "l"(a), "l"(b)); return d;
}
__device__ __forceinline__ ull add2(ull a, ull b) {
    ull d; asm("add.rn.f32x2 %0, %1, %2;" : "=l"(d) : "l"(a), "l"(b)); return d;
}
// monotone float->uint map (handles tiny negatives from cancellation)
__device__ __forceinline__ unsigned mono(float f) {
    unsigned b = __float_as_uint(f);
    return (b & 0x80000000u) ? ~b : (b | 0x80000000u);
}

// ---- KNN prep: pack refs + |r|^2, reference rounding: fl(fl(x2+y2)+z2) ----
__global__ void prep_kernel(const float* __restrict__ t1) {
    int p = blockIdx.x * 256 + threadIdx.x;
    if (p >= NPTS / 2) return;
    int i0 = 2 * p, i1 = i0 + 1;
    float x0 = t1[i0], y0 = t1[NPTS + i0], z0 = t1[2 * NPTS + i0];
    float x1 = t1[i1], y1 = t1[NPTS + i1], z1 = t1[2 * NPTS + i1];
    float r20 = __fadd_rn(__fadd_rn(__fmul_rn(x0, x0), __fmul_rn(y0, y0)), __fmul_rn(z0, z0));
    float r21 = __fadd_rn(__fadd_rn(__fmul_rn(x1, x1), __fmul_rn(y1, y1)), __fmul_rn(z1, z1));
    ulonglong2 e0, e1;
    e0.x = pack2(x0, x1); e0.y = pack2(y0, y1);
    e1.x = pack2(z0, z1); e1.y = pack2(r20, r21);
    g_refp[p][0] = e0;
    g_refp[p][1] = e1;
}

// ---- KNN partial argmin: group-min filter + rare exact first-index scan ----
__global__ void __launch_bounds__(256)
knn_partial_kernel(const float* __restrict__ t2) {
    __shared__ ulonglong2 s_ref[SEGREFS / 2][2];
    const int tid = threadIdx.x;
    const int seg = blockIdx.y;
    s_ref[tid >> 1][tid & 1] = g_refp[seg * (SEGREFS / 2) + (tid >> 1)][tid & 1];

    const int q0 = blockIdx.x * 512 + tid;
    ull axn[2], ayn[2], azn[2], q2p[2];
#pragma unroll
    for (int s = 0; s < 2; ++s) {
        int q = q0 + s * 256;
        float qx = t2[q], qy = t2[NPTS + q], qz = t2[2 * NPTS + q];
        float q2 = __fadd_rn(__fadd_rn(__fmul_rn(qx, qx), __fmul_rn(qy, qy)), __fmul_rn(qz, qz));
        float ax = __fmul_rn(qx, -2.0f), ay = __fmul_rn(qy, -2.0f), az = __fmul_rn(qz, -2.0f);
        axn[s] = pack2(ax, ax); ayn[s] = pack2(ay, ay); azn[s] = pack2(az, az);
        q2p[s] = pack2(q2, q2);
    }
    float best[2]; int bi[2];
    best[0] = best[1] = __int_as_float(0x7f800000);
    bi[0] = bi[1] = 0x7fffffff;
    __syncthreads();

    const int gbase = seg * SEGREFS;
    for (int g = 0; g < SEGREFS / 16; ++g) {
        ull d[2][8];
#pragma unroll
        for (int p8 = 0; p8 < 8; ++p8) {
            const ulonglong2 e0 = s_ref[g * 8 + p8][0];
            const ulonglong2 e1 = s_ref[g * 8 + p8][1];
#pragma unroll
            for (int s = 0; s < 2; ++s) {
                // d = fl(fl(r2+q2) + fma(z,-2Z, fma(y,-2Y, x*(-2X)))) : exact ref rounding
                d[s][p8] = add2(add2(e1.y, q2p[s]),
                                fma2(e1.x, azn[s], fma2(e0.y, ayn[s], mul2(e0.x, axn[s]))));
            }
        }
#pragma unroll
        for (int s = 0; s < 2; ++s) {
            float mp[8];
#pragma unroll
            for (int p8 = 0; p8 < 8; ++p8) {
                float lo, hi; unpack2(d[s][p8], lo, hi);
                mp[p8] = fminf(lo, hi);
            }
            float m = fminf(fminf(fminf(mp[0], mp[1]), fminf(mp[2], mp[3])),
                            fminf(fminf(mp[4], mp[5]), fminf(mp[6], mp[7])));
            if (m < best[s]) {   // rare: exact first-index sequential scan
                const int ib = gbase + g * 16;
#pragma unroll
                for (int p8 = 0; p8 < 8; ++p8) {
                    float lo, hi; unpack2(d[s][p8], lo, hi);
                    if (lo < best[s]) { best[s] = lo; bi[s] = ib + 2 * p8; }
                    if (hi < best[s]) { best[s] = hi; bi[s] = ib + 2 * p8 + 1; }
                }
            }
        }
    }
#pragma unroll
    for (int s = 0; s < 2; ++s) {
        ull key = ((ull)mono(best[s]) << 32) | (unsigned)bi[s];
        g_part[(size_t)seg * NPTS + q0 + s * 256] = key;
    }
}

__global__ void knn_reduce_kernel() {
    int q = blockIdx.x * 256 + threadIdx.x;
    ull m = ~0ull;
#pragma unroll
    for (int s = 0; s < SEGS; ++s) {
        ull v = g_part[(size_t)s * NPTS + q];
        if (v < m) m = v;
    }
    g_idx[q] = (int)(unsigned)(m & 0xffffffffu);
}

// ---- gather + concat: g_emb = [emb1[:, idx] ; emb2] ----
__global__ void gather_kernel(const float* __restrict__ emb1, const float* __restrict__ emb2) {
    int n = blockIdx.x * 256 + threadIdx.x;
    int k = blockIdx.y;
    float v = (k < FDIM) ? emb1[k * NPTS + g_idx[n]] : emb2[(k - FDIM) * NPTS + n];
    g_emb[k * NPTS + n] = v;
}

// ---- GEMM + bias + relu: Y = relu(W @ X + b); dual branch via blockIdx.z ----
// Tile TM x 128, BK=16, 256 threads. W smem stored as duplicated packed (w,w)
// ull pairs so hot-loop W reads are LDS.128 (2 m-rows, broadcast = 1 phase).
template<int TM>
__global__ void __launch_bounds__(256)
gemm_relu_kernel(const float* __restrict__ W0, const float* __restrict__ B0,
                 const float* __restrict__ X0, float* __restrict__ Y0,
                 const float* __restrict__ W1, const float* __restrict__ B1,
                 const float* __restrict__ X1, float* __restrict__ Y1,
                 int K) {
    constexpr int MI = TM / 16;                 // m-rows per thread
    __shared__ __align__(16) ull Ws2[16][TM + 2];
    __shared__ __align__(16) ull Xs[16][64];
    const int tid = threadIdx.x;
    const float* W  = blockIdx.z ? W1 : W0;
    const float* Bi = blockIdx.z ? B1 : B0;
    const float* X  = blockIdx.z ? X1 : X0;
    float*       Y  = blockIdx.z ? Y1 : Y0;
    const int m0 = blockIdx.y * TM;
    const int n0 = blockIdx.x * 128;
    const int tm  = (tid >> 4) * MI;
    const int tn2 = (tid & 15) * 4;             // 4 packed pairs = 8 n's

    ull acc[MI][4];
#pragma unroll
    for (int i = 0; i < MI; ++i)
#pragma unroll
        for (int j = 0; j < 4; ++j) acc[i][j] = 0ull;

    for (int k0 = 0; k0 < K; k0 += 16) {
        // W tile: TM x 16 floats; each thread handles a 2m x 4k block -> STS.128
#pragma unroll
        for (int id = tid; id < TM * 2; id += 256) {
            int mp = id >> 2, kq = id & 3;
            int m = mp * 2;
            const float4 wa = *(const float4*)&W[(size_t)(m0 + m) * K + k0 + kq * 4];
            const float4 wb = *(const float4*)&W[(size_t)(m0 + m + 1) * K + k0 + kq * 4];
            ulonglong2 v;
            v.x = pack2(wa.x, wa.x); v.y = pack2(wb.x, wb.x);
            *(ulonglong2*)&Ws2[kq * 4 + 0][m] = v;
            v.x = pack2(wa.y, wa.y); v.y = pack2(wb.y, wb.y);
            *(ulonglong2*)&Ws2[kq * 4 + 1][m] = v;
            v.x = pack2(wa.z, wa.z); v.y = pack2(wb.z, wb.z);
            *(ulonglong2*)&Ws2[kq * 4 + 2][m] = v;
            v.x = pack2(wa.w, wa.w); v.y = pack2(wb.w, wb.w);
            *(ulonglong2*)&Ws2[kq * 4 + 3][m] = v;
        }
        // X tile: 16 x 128 floats (already pair-packed in memory layout)
#pragma unroll
        for (int j = 0; j < 2; ++j) {
            int id = j * 256 + tid;
            int row = id >> 5, c2 = id & 31;
            ((ulonglong2*)&Xs[row][0])[c2] =
                ((const ulonglong2*)&X[(size_t)(k0 + row) * NPTS + n0])[c2];
        }
        __syncthreads();
#pragma unroll
        for (int kk = 0; kk < 16; ++kk) {
            ull x[4];
            ulonglong2 xa = *(const ulonglong2*)&Xs[kk][tn2];
            ulonglong2 xb = *(const ulonglong2*)&Xs[kk][tn2 + 2];
            x[0] = xa.x; x[1] = xa.y; x[2] = xb.x; x[3] = xb.y;
#pragma unroll
            for (int ii = 0; ii < MI / 2; ++ii) {
                ulonglong2 wp = *(const ulonglong2*)&Ws2[kk][tm + 2 * ii];
#pragma unroll
                for (int j = 0; j < 4; ++j) acc[2 * ii][j]     = fma2(wp.x, x[j], acc[2 * ii][j]);
#pragma unroll
                for (int j = 0; j < 4; ++j) acc[2 * ii + 1][j] = fma2(wp.y, x[j], acc[2 * ii + 1][j]);
            }
        }
        __syncthreads();
    }
#pragma unroll
    for (int i = 0; i < MI; ++i) {
        float b = Bi[m0 + tm + i];
        float* yr = &Y[(size_t)(m0 + tm + i) * NPTS + n0 + tn2 * 2];
        float v[8];
#pragma unroll
        for (int j = 0; j < 4; ++j) {
            float lo, hi; unpack2(acc[i][j], lo, hi);
            v[2 * j]     = fmaxf(lo + b, 0.0f);
            v[2 * j + 1] = fmaxf(hi + b, 0.0f);
        }
        *(float4*)&yr[0] = make_float4(v[0], v[1], v[2], v[3]);
        *(float4*)&yr[4] = make_float4(v[4], v[5], v[6], v[7]);
    }
}

// ---- layer 4: only obj-selected rows, no relu ----
__global__ void __launch_bounds__(256)
final_kernel(const float* __restrict__ w4r, const float* __restrict__ b4r,
             const float* __restrict__ w4t, const float* __restrict__ b4t,
             const int* __restrict__ obj, float* __restrict__ out) {
    __shared__ float wr[4][128], wt[3][128];
    const int tid = threadIdx.x;
    const int o = obj[0];
    if (tid < 128) {
#pragma unroll
        for (int q = 0; q < 4; ++q) wr[q][tid] = w4r[(size_t)(o * 4 + q) * 128 + tid];
#pragma unroll
        for (int q = 0; q < 3; ++q) wt[q][tid] = w4t[(size_t)(o * 3 + q) * 128 + tid];
    }
    __syncthreads();
    const int n = blockIdx.x * 256 + tid;
    float ar[4], at[3];
#pragma unroll
    for (int q = 0; q < 4; ++q) ar[q] = b4r[o * 4 + q];
#pragma unroll
    for (int q = 0; q < 3; ++q) at[q] = b4t[o * 3 + q];
    for (int k = 0; k < 128; ++k) {
        float xr = g_h3[0][(size_t)k * NPTS + n];
        float xt = g_h3[1][(size_t)k * NPTS + n];
#pragma unroll
        for (int q = 0; q < 4; ++q) ar[q] = fmaf(wr[q][k], xr, ar[q]);
#pragma unroll
        for (int q = 0; q < 3; ++q) at[q] = fmaf(wt[q][k], xt, at[q]);
    }
#pragma unroll
    for (int q = 0; q < 4; ++q) out[(size_t)n * 4 + q] = ar[q];
    float* ot = out + 4 * NPTS;
#pragma unroll
    for (int q = 0; q < 3; ++q) ot[(size_t)n * 3 + q] = at[q];
}

extern "C" void kernel_launch(void* const* d_in, const int* in_sizes, int n_in,
                              void* d_out, int out_size) {
    const float* emb1 = (const float*)d_in[0];
    const float* emb2 = (const float*)d_in[1];
    const float* t1   = (const float*)d_in[2];
    const float* t2   = (const float*)d_in[3];
    const int*   obj  = (const int*)d_in[4];
    const float* w1r = (const float*)d_in[5],  *b1r = (const float*)d_in[6];
    const float* w2r = (const float*)d_in[7],  *b2r = (const float*)d_in[8];
    const float* w3r = (const float*)d_in[9],  *b3r = (const float*)d_in[10];
    const float* w4r = (const float*)d_in[11], *b4r = (const float*)d_in[12];
    const float* w1t = (const float*)d_in[13], *b1t = (const float*)d_in[14];
    const float* w2t = (const float*)d_in[15], *b2t = (const float*)d_in[16];
    const float* w3t = (const float*)d_in[17], *b3t = (const float*)d_in[18];
    const float* w4t = (const float*)d_in[19], *b4t = (const float*)d_in[20];
    float* out = (float*)d_out;

    float *p_emb, *p_h1, *p_h2, *p_h3;
    cudaGetSymbolAddress((void**)&p_emb, g_emb);
    cudaGetSymbolAddress((void**)&p_h1, g_h1);
    cudaGetSymbolAddress((void**)&p_h2, g_h2);
    cudaGetSymbolAddress((void**)&p_h3, g_h3);
    float* h1r = p_h1;              float* h1t = p_h1 + 640 * NPTS;
    float* h2r = p_h2;              float* h2t = p_h2 + 256 * NPTS;
    float* h3r = p_h3;              float* h3t = p_h3 + 128 * NPTS;

    prep_kernel<<<(NPTS / 2 + 255) / 256, 256>>>(t1);
    knn_partial_kernel<<<dim3(16, SEGS), 256>>>(t2);
    knn_reduce_kernel<<<NPTS / 256, 256>>>();
    gather_kernel<<<dim3(NPTS / 256, 1024), 256>>>(emb1, emb2);

    gemm_relu_kernel<128><<<dim3(64, 5, 2), 256>>>(w1r, b1r, p_emb, h1r,
                                                   w1t, b1t, p_emb, h1t, 1024);
    gemm_relu_kernel<128><<<dim3(64, 2, 2), 256>>>(w2r, b2r, h1r, h2r,
                                                   w2t, b2t, h1t, h2t, 640);
    gemm_relu_kernel<64><<<dim3(64, 2, 2), 256>>>(w3r, b3r, h2r, h3r,
                                                  w3t, b3t, h2t, h3t, 256);

    final_kernel<<<NPTS / 256, 256>>>(w4r, b4r, w4t, b4t, obj, out);
}

// round 14
// speedup vs baseline: 2.4629x; 2.4629x over previous
#include <cuda_runtime.h>
#include <cuda_bf16.h>
#include <cstdint>

#define NPTS 8192
#define SEGS 32
#define SEGREFS 256

typedef unsigned long long ull;

// ================= device scratch (no allocations allowed) =================
__device__ int        g_idx[NPTS];
__device__ ulonglong2 g_refp[NPTS / 2][2];     // {x01,y01},{z01,r2_01}
__device__ ull        g_part[SEGS * NPTS];

__device__ __nv_bfloat16 g_xh[NPTS * 1024], g_xl[NPTS * 1024];          // layer1 input (N,K)
__device__ __nv_bfloat16 g_y1h[2][NPTS * 640], g_y1l[2][NPTS * 640];
__device__ __nv_bfloat16 g_y2h[2][NPTS * 256], g_y2l[2][NPTS * 256];
__device__ float         g_h3f[2][NPTS * 128];                           // (N,128) fp32
__device__ __nv_bfloat16 g_w1h[2][640 * 1024], g_w1l[2][640 * 1024];
__device__ __nv_bfloat16 g_w2h[2][256 * 640],  g_w2l[2][256 * 640];
__device__ __nv_bfloat16 g_w3h[2][128 * 256],  g_w3l[2][128 * 256];

// ================= helpers =================
__device__ __forceinline__ ull pack2(float lo, float hi) {
    ull r; asm("mov.b64 %0, {%1, %2};" : "=l"(r) : "f"(lo), "f"(hi)); return r;
}
__device__ __forceinline__ void unpack2(ull v, float& lo, float& hi) {
    asm("mov.b64 {%0, %1}, %2;" : "=f"(lo), "=f"(hi) : "l"(v));
}
__device__ __forceinline__ ull fma2(ull a, ull b, ull c) {
    ull d; asm("fma.rn.f32x2 %0, %1, %2, %3;" : "=l"(d) : "l"(a), "l"(b), "l"(c)); return d;
}
__device__ __forceinline__ ull mul2(ull a, ull b) {
    ull d; asm("mul.rn.f32x2 %0, %1, %2;" : "=l"(d) : "l"(a), "l"(b)); return d;
}
__device__ __forceinline__ ull add2(ull a, ull b) {
    ull d; asm("add.rn.f32x2 %0, %1, %2;" : "=l"(d) : "l"(a), "l"(b)); return d;
}
__device__ __forceinline__ unsigned mono(float f) {
    unsigned b = __float_as_uint(f);
    return (b & 0x80000000u) ? ~b : (b | 0x80000000u);
}
__device__ __forceinline__ uint32_t smem_u32(const void* p) {
    uint32_t a;
    asm("{ .reg .u64 t; cvta.to.shared.u64 t, %1; cvt.u32.u64 %0, t; }" : "=r"(a) : "l"(p));
    return a;
}
__device__ __forceinline__ void cp16(uint32_t s, const void* g) {
    asm volatile("cp.async.cg.shared.global [%0], [%1], 16;" :: "r"(s), "l"(g));
}
#define CP_COMMIT()  asm volatile("cp.async.commit_group;" ::: "memory")
#define CP_WAIT0()   asm volatile("cp.async.wait_group 0;" ::: "memory")

#define LDSM4(R, A) \
    asm volatile("ldmatrix.sync.aligned.m8n8.x4.shared.b16 {%0,%1,%2,%3}, [%4];" \
                 : "=r"((R)[0]), "=r"((R)[1]), "=r"((R)[2]), "=r"((R)[3]) : "r"(A))

#define MMA_BF16(C, A, B) \
    asm volatile("mma.sync.aligned.m16n8k16.row.col.f32.bf16.bf16.f32 " \
                 "{%0,%1,%2,%3}, {%4,%5,%6,%7}, {%8,%9}, {%0,%1,%2,%3};" \
                 : "+f"((C)[0]), "+f"((C)[1]), "+f"((C)[2]), "+f"((C)[3]) \
                 : "r"((A)[0]), "r"((A)[1]), "r"((A)[2]), "r"((A)[3]), \
                   "r"((B)[0]), "r"((B)[1]))

// ================= KNN (proven R5 version, bit-exact vs reference) =================
__global__ void prep_kernel(const float* __restrict__ t1) {
    int p = blockIdx.x * 256 + threadIdx.x;
    if (p >= NPTS / 2) return;
    int i0 = 2 * p, i1 = i0 + 1;
    float x0 = t1[i0], y0 = t1[NPTS + i0], z0 = t1[2 * NPTS + i0];
    float x1 = t1[i1], y1 = t1[NPTS + i1], z1 = t1[2 * NPTS + i1];
    float r20 = __fadd_rn(__fadd_rn(__fmul_rn(x0, x0), __fmul_rn(y0, y0)), __fmul_rn(z0, z0));
    float r21 = __fadd_rn(__fadd_rn(__fmul_rn(x1, x1), __fmul_rn(y1, y1)), __fmul_rn(z1, z1));
    ulonglong2 e0, e1;
    e0.x = pack2(x0, x1); e0.y = pack2(y0, y1);
    e1.x = pack2(z0, z1); e1.y = pack2(r20, r21);
    g_refp[p][0] = e0;
    g_refp[p][1] = e1;
}

__global__ void __launch_bounds__(256)
knn_partial_kernel(const float* __restrict__ t2) {
    __shared__ ulonglong2 s_ref[SEGREFS / 2][2];
    const int tid = threadIdx.x;
    const int seg = blockIdx.y;
    s_ref[tid >> 1][tid & 1] = g_refp[seg * (SEGREFS / 2) + (tid >> 1)][tid & 1];

    const int q0 = blockIdx.x * 512 + tid;
    ull axn[2], ayn[2], azn[2], q2p[2];
#pragma unroll
    for (int s = 0; s < 2; ++s) {
        int q = q0 + s * 256;
        float qx = t2[q], qy = t2[NPTS + q], qz = t2[2 * NPTS + q];
        float q2 = __fadd_rn(__fadd_rn(__fmul_rn(qx, qx), __fmul_rn(qy, qy)), __fmul_rn(qz, qz));
        float ax = __fmul_rn(qx, -2.0f), ay = __fmul_rn(qy, -2.0f), az = __fmul_rn(qz, -2.0f);
        axn[s] = pack2(ax, ax); ayn[s] = pack2(ay, ay); azn[s] = pack2(az, az);
        q2p[s] = pack2(q2, q2);
    }
    float best[2][8]; int bi[2][8];
#pragma unroll
    for (int s = 0; s < 2; ++s)
#pragma unroll
        for (int c = 0; c < 8; ++c) { best[s][c] = __int_as_float(0x7f800000); bi[s][c] = 0x7fffffff; }
    __syncthreads();

    const int gbase = seg * SEGREFS;
    for (int pg = 0; pg < SEGREFS / 2; pg += 4) {
#pragma unroll
        for (int u = 0; u < 4; ++u) {
            const int p = pg + u;
            const ulonglong2 e0 = s_ref[p][0];
            const ulonglong2 e1 = s_ref[p][1];
            const int ib = gbase + p * 2;
#pragma unroll
            for (int s = 0; s < 2; ++s) {
                ull g2 = fma2(e1.x, azn[s], fma2(e0.y, ayn[s], mul2(e0.x, axn[s])));
                ull sv = add2(e1.y, q2p[s]);
                ull d  = add2(sv, g2);
                float dlo, dhi; unpack2(d, dlo, dhi);
                if (dlo < best[s][2 * u])     { best[s][2 * u] = dlo;     bi[s][2 * u] = ib; }
                if (dhi < best[s][2 * u + 1]) { best[s][2 * u + 1] = dhi; bi[s][2 * u + 1] = ib + 1; }
            }
        }
    }
#pragma unroll
    for (int s = 0; s < 2; ++s) {
        ull m = ~0ull;
#pragma unroll
        for (int c = 0; c < 8; ++c) {
            ull key = ((ull)mono(best[s][c]) << 32) | (unsigned)bi[s][c];
            if (key < m) m = key;
        }
        g_part[(size_t)seg * NPTS + q0 + s * 256] = m;
    }
}

__global__ void knn_reduce_kernel() {
    int q = blockIdx.x * 256 + threadIdx.x;
    ull m = ~0ull;
#pragma unroll
    for (int s = 0; s < SEGS; ++s) {
        ull v = g_part[(size_t)s * NPTS + q];
        if (v < m) m = v;
    }
    g_idx[q] = (int)(unsigned)(m & 0xffffffffu);
}

// ============ gather + transpose + bf16 split: X1[n][k] hi/lo ============
__global__ void __launch_bounds__(256)
gather_split_kernel(const float* __restrict__ emb1, const float* __restrict__ emb2) {
    __shared__ float tile[32][33];
    const int tx = threadIdx.x & 31, ty = threadIdx.x >> 5;
    const int n0 = blockIdx.x * 32, k0 = blockIdx.y * 32;
#pragma unroll
    for (int r = 0; r < 4; ++r) {
        int k = k0 + ty * 4 + r;
        int n = n0 + tx;
        float v = (k < 512) ? emb1[k * NPTS + g_idx[n]] : emb2[(k - 512) * NPTS + n];
        tile[ty * 4 + r][tx] = v;
    }
    __syncthreads();
#pragma unroll
    for (int r = 0; r < 4; ++r) {
        int nl = ty * 4 + r;
        float v = tile[tx][nl];
        __nv_bfloat16 h = __float2bfloat16(v);
        __nv_bfloat16 l = __float2bfloat16(v - __bfloat162float(h));
        size_t o = (size_t)(n0 + nl) * 1024 + k0 + tx;
        g_xh[o] = h; g_xl[o] = l;
    }
}

// ============ weight bf16 split (one launch per branch) ============
__global__ void __launch_bounds__(256)
split_w_kernel(const float* __restrict__ w1, const float* __restrict__ w2,
               const float* __restrict__ w3, int z) {
    int i = blockIdx.x * 256 + threadIdx.x;
    if (i < 640 * 1024) {
        float v = w1[i]; __nv_bfloat16 h = __float2bfloat16(v);
        g_w1h[z][i] = h; g_w1l[z][i] = __float2bfloat16(v - __bfloat162float(h));
    }
    if (i < 256 * 640) {
        float v = w2[i]; __nv_bfloat16 h = __float2bfloat16(v);
        g_w2h[z][i] = h; g_w2l[z][i] = __float2bfloat16(v - __bfloat162float(h));
    }
    if (i < 128 * 256) {
        float v = w3[i]; __nv_bfloat16 h = __float2bfloat16(v);
        g_w3h[z][i] = h; g_w3l[z][i] = __float2bfloat16(v - __bfloat162float(h));
    }
}

// ================= warp-MMA bf16-split GEMM + bias + relu =================
// D[n,m] = sum_k X[n,k]*W[m,k]. CTA tile 128n x 128m, 8 warps (64n x 32m each),
// BK=32, double-buffered cp.async. 3 passes: Xh*Wh + Xh*Wl + Xl*Wh (fp32 acc).
#define TS      10240                 // one tile: 128 rows x 80B
#define BUFSZ   (4 * TS)              // Xh,Xl,Wh,Wl
#define MSM_TOT (1024 + 2 * BUFSZ)    // bias + 2 buffers = 82944 B

template<int K>
__device__ __forceinline__ void issue_chunk(uint32_t sb, int buf,
        const __nv_bfloat16* Xh, const __nv_bfloat16* Xl,
        const __nv_bfloat16* Wh, const __nv_bfloat16* Wl,
        int n0, int m0, int k0, int tid) {
    const int r  = tid >> 1;
    const int cb = (tid & 1) * 32;
    const size_t xoff = ((size_t)(n0 + r) * K + k0) * 2 + cb;
    const size_t woff = ((size_t)(m0 + r) * K + k0) * 2 + cb;
    const uint32_t s = sb + 1024 + (uint32_t)buf * BUFSZ + r * 80 + cb;
    cp16(s,               (const char*)Xh + xoff);
    cp16(s + 16,          (const char*)Xh + xoff + 16);
    cp16(s + TS,          (const char*)Xl + xoff);
    cp16(s + TS + 16,     (const char*)Xl + xoff + 16);
    cp16(s + 2 * TS,      (const char*)Wh + woff);
    cp16(s + 2 * TS + 16, (const char*)Wh + woff + 16);
    cp16(s + 3 * TS,      (const char*)Wl + woff);
    cp16(s + 3 * TS + 16, (const char*)Wl + woff + 16);
    CP_COMMIT();
}

template<int LAYER>
__global__ void __launch_bounds__(256, 1)
mma_gemm_kernel(const float* __restrict__ bias0, const float* __restrict__ bias1) {
    extern __shared__ char sm[];
    constexpr int K  = (LAYER == 1) ? 1024 : (LAYER == 2) ? 640 : 256;
    constexpr int M  = (LAYER == 1) ? 640  : (LAYER == 2) ? 256 : 128;
    constexpr int NC = K / 32;
    const int tid = threadIdx.x, lane = tid & 31, wid = tid >> 5;
    const int z  = blockIdx.z;
    const int n0 = blockIdx.x * 128, m0 = blockIdx.y * 128;

    const __nv_bfloat16 *Xh, *Xl, *Wh, *Wl;
    __nv_bfloat16 *Yh = nullptr, *Yl = nullptr;
    float* Yf = nullptr;
    if constexpr (LAYER == 1) { Xh = g_xh;     Xl = g_xl;     Wh = g_w1h[z]; Wl = g_w1l[z];
                                Yh = g_y1h[z]; Yl = g_y1l[z]; }
    if constexpr (LAYER == 2) { Xh = g_y1h[z]; Xl = g_y1l[z]; Wh = g_w2h[z]; Wl = g_w2l[z];
                                Yh = g_y2h[z]; Yl = g_y2l[z]; }
    if constexpr (LAYER == 3) { Xh = g_y2h[z]; Xl = g_y2l[z]; Wh = g_w3h[z]; Wl = g_w3l[z];
                                Yf = g_h3f[z]; }
    const float* Bi = z ? bias1 : bias0;

    float* sbias = (float*)sm;
    if (tid < 128) sbias[tid] = Bi[m0 + tid];
    const uint32_t sb = smem_u32(sm);

    const int warp_n = (wid & 1) * 64;
    const int warp_m = (wid >> 1) * 32;

    float acc[4][4][4];
#pragma unroll
    for (int ni = 0; ni < 4; ++ni)
#pragma unroll
        for (int mi = 0; mi < 4; ++mi)
#pragma unroll
            for (int j = 0; j < 4; ++j) acc[ni][mi][j] = 0.0f;

    // per-lane ldmatrix address components
    const int a_row = warp_n + (lane & 15);
    const int a_col = (lane >> 4) * 8;                    // halves
    const int b_row = warp_m + ((lane >> 4) << 3) + (lane & 7);
    const int b_col = ((lane >> 3) & 1) * 8;              // halves

    issue_chunk<K>(sb, 0, Xh, Xl, Wh, Wl, n0, m0, 0, tid);

    for (int c = 0; c < NC; ++c) {
        CP_WAIT0();
        __syncthreads();
        if (c + 1 < NC)
            issue_chunk<K>(sb, (c + 1) & 1, Xh, Xl, Wh, Wl, n0, m0, (c + 1) * 32, tid);

        const uint32_t xb = sb + 1024 + (uint32_t)(c & 1) * BUFSZ;
        const uint32_t wb = xb + 2 * TS;
#pragma unroll
        for (int ks = 0; ks < 2; ++ks) {
            const int kh = ks * 16;
            uint32_t ah[4][4], al[4][4];
#pragma unroll
            for (int ni = 0; ni < 4; ++ni) {
                uint32_t ad = xb + (a_row + ni * 16) * 80 + (kh + a_col) * 2;
                LDSM4(ah[ni], ad);
                LDSM4(al[ni], ad + TS);
            }
            uint32_t bh[4][2], bl[4][2];
#pragma unroll
            for (int mp = 0; mp < 2; ++mp) {
                uint32_t bd = wb + (b_row + mp * 16) * 80 + (kh + b_col) * 2;
                uint32_t t[4];
                LDSM4(t, bd);
                bh[2 * mp][0] = t[0]; bh[2 * mp][1] = t[1];
                bh[2 * mp + 1][0] = t[2]; bh[2 * mp + 1][1] = t[3];
                LDSM4(t, bd + TS);
                bl[2 * mp][0] = t[0]; bl[2 * mp][1] = t[1];
                bl[2 * mp + 1][0] = t[2]; bl[2 * mp + 1][1] = t[3];
            }
#pragma unroll
            for (int ni = 0; ni < 4; ++ni)
#pragma unroll
                for (int mi = 0; mi < 4; ++mi) {
                    MMA_BF16(acc[ni][mi], ah[ni], bh[mi]);
                    MMA_BF16(acc[ni][mi], ah[ni], bl[mi]);
                    MMA_BF16(acc[ni][mi], al[ni], bh[mi]);
                }
        }
    }
    __syncthreads();

    // epilogue: c0:(r, c) c1:(r, c+1) c2:(r+8, c) c3:(r+8, c+1)
    const int erow = lane >> 2, ecol = (lane & 3) * 2;
#pragma unroll
    for (int ni = 0; ni < 4; ++ni) {
#pragma unroll
        for (int mi = 0; mi < 4; ++mi) {
            const int n  = n0 + warp_n + ni * 16 + erow;
            const int ml = warp_m + mi * 8 + ecol;           // m within 128-tile
            const int m  = m0 + ml;
            float v0 = acc[ni][mi][0] + sbias[ml];
            float v1 = acc[ni][mi][1] + sbias[ml + 1];
            float v2 = acc[ni][mi][2] + sbias[ml];
            float v3 = acc[ni][mi][3] + sbias[ml + 1];
            v0 = fmaxf(v0, 0.f); v1 = fmaxf(v1, 0.f);
            v2 = fmaxf(v2, 0.f); v3 = fmaxf(v3, 0.f);
            if constexpr (LAYER == 3) {
                *(float2*)&Yf[(size_t)n * 128 + m]       = make_float2(v0, v1);
                *(float2*)&Yf[(size_t)(n + 8) * 128 + m] = make_float2(v2, v3);
            } else {
                __nv_bfloat162 h0 = __floats2bfloat162_rn(v0, v1);
                __nv_bfloat162 l0 = __floats2bfloat162_rn(v0 - __bfloat162float(h0.x),
                                                          v1 - __bfloat162float(h0.y));
                __nv_bfloat162 h1 = __floats2bfloat162_rn(v2, v3);
                __nv_bfloat162 l1 = __floats2bfloat162_rn(v2 - __bfloat162float(h1.x),
                                                          v3 - __bfloat162float(h1.y));
                *(__nv_bfloat162*)&Yh[(size_t)n * M + m]       = h0;
                *(__nv_bfloat162*)&Yl[(size_t)n * M + m]       = l0;
                *(__nv_bfloat162*)&Yh[(size_t)(n + 8) * M + m] = h1;
                *(__nv_bfloat162*)&Yl[(size_t)(n + 8) * M + m] = l1;
            }
        }
    }
}

// ================= layer 4: obj-selected rows only, no relu =================
__global__ void __launch_bounds__(256)
final_kernel(const float* __restrict__ w4r, const float* __restrict__ b4r,
             const float* __restrict__ w4t, const float* __restrict__ b4t,
             const int* __restrict__ obj, float* __restrict__ out) {
    __shared__ float wr[4][128], wt[3][128];
    const int tid = threadIdx.x;
    const int o = obj[0];
    if (tid < 128) {
#pragma unroll
        for (int q = 0; q < 4; ++q) wr[q][tid] = w4r[(size_t)(o * 4 + q) * 128 + tid];
#pragma unroll
        for (int q = 0; q < 3; ++q) wt[q][tid] = w4t[(size_t)(o * 3 + q) * 128 + tid];
    }
    __syncthreads();
    const int n = blockIdx.x * 256 + tid;
    float ar[4], at[3];
#pragma unroll
    for (int q = 0; q < 4; ++q) ar[q] = b4r[o * 4 + q];
#pragma unroll
    for (int q = 0; q < 3; ++q) at[q] = b4t[o * 3 + q];
    const float4* xr = (const float4*)&g_h3f[0][(size_t)n * 128];
    const float4* xt = (const float4*)&g_h3f[1][(size_t)n * 128];
#pragma unroll 4
    for (int kb = 0; kb < 32; ++kb) {
        float4 x = xr[kb];
        float4 y = xt[kb];
#pragma unroll
        for (int q = 0; q < 4; ++q) {
            ar[q] = fmaf(wr[q][4 * kb + 0], x.x, ar[q]);
            ar[q] = fmaf(wr[q][4 * kb + 1], x.y, ar[q]);
            ar[q] = fmaf(wr[q][4 * kb + 2], x.z, ar[q]);
            ar[q] = fmaf(wr[q][4 * kb + 3], x.w, ar[q]);
        }
#pragma unroll
        for (int q = 0; q < 3; ++q) {
            at[q] = fmaf(wt[q][4 * kb + 0], y.x, at[q]);
            at[q] = fmaf(wt[q][4 * kb + 1], y.y, at[q]);
            at[q] = fmaf(wt[q][4 * kb + 2], y.z, at[q]);
            at[q] = fmaf(wt[q][4 * kb + 3], y.w, at[q]);
        }
    }
#pragma unroll
    for (int q = 0; q < 4; ++q) out[(size_t)n * 4 + q] = ar[q];
    float* ot = out + 4 * NPTS;
#pragma unroll
    for (int q = 0; q < 3; ++q) ot[(size_t)n * 3 + q] = at[q];
}

// ================= launch =================
extern "C" void kernel_launch(void* const* d_in, const int* in_sizes, int n_in,
                              void* d_out, int out_size) {
    const float* emb1 = (const float*)d_in[0];
    const float* emb2 = (const float*)d_in[1];
    const float* t1   = (const float*)d_in[2];
    const float* t2   = (const float*)d_in[3];
    const int*   obj  = (const int*)d_in[4];
    const float* w1r = (const float*)d_in[5],  *b1r = (const float*)d_in[6];
    const float* w2r = (const float*)d_in[7],  *b2r = (const float*)d_in[8];
    const float* w3r = (const float*)d_in[9],  *b3r = (const float*)d_in[10];
    const float* w4r = (const float*)d_in[11], *b4r = (const float*)d_in[12];
    const float* w1t = (const float*)d_in[13], *b1t = (const float*)d_in[14];
    const float* w2t = (const float*)d_in[15], *b2t = (const float*)d_in[16];
    const float* w3t = (const float*)d_in[17], *b3t = (const float*)d_in[18];
    const float* w4t = (const float*)d_in[19], *b4t = (const float*)d_in[20];
    float* out = (float*)d_out;

    cudaFuncSetAttribute(mma_gemm_kernel<1>, cudaFuncAttributeMaxDynamicSharedMemorySize, MSM_TOT);
    cudaFuncSetAttribute(mma_gemm_kernel<2>, cudaFuncAttributeMaxDynamicSharedMemorySize, MSM_TOT);
    cudaFuncSetAttribute(mma_gemm_kernel<3>, cudaFuncAttributeMaxDynamicSharedMemorySize, MSM_TOT);

    split_w_kernel<<<(640 * 1024 + 255) / 256, 256>>>(w1r, w2r, w3r, 0);
    split_w_kernel<<<(640 * 1024 + 255) / 256, 256>>>(w1t, w2t, w3t, 1);

    prep_kernel<<<(NPTS / 2 + 255) / 256, 256>>>(t1);
    knn_partial_kernel<<<dim3(16, SEGS), 256>>>(t2);
    knn_reduce_kernel<<<NPTS / 256, 256>>>();
    gather_split_kernel<<<dim3(NPTS / 32, 1024 / 32), 256>>>(emb1, emb2);

    mma_gemm_kernel<1><<<dim3(64, 5, 2), 256, MSM_TOT>>>(b1r, b1t);
    mma_gemm_kernel<2><<<dim3(64, 2, 2), 256, MSM_TOT>>>(b2r, b2t);
    mma_gemm_kernel<3><<<dim3(64, 1, 2), 256, MSM_TOT>>>(b3r, b3t);

    final_kernel<<<NPTS / 256, 256>>>(w4r, b4r, w4t, b4t, obj, out);
}